// round 3
// baseline (speedup 1.0000x reference)
#include <cuda_runtime.h>
#include <cstdint>

typedef unsigned long long ull;

__device__ __forceinline__ ull pack2(float lo, float hi) {
    ull r; asm("mov.b64 %0, {%1, %2};" : "=l"(r) : "f"(lo), "f"(hi)); return r;
}
__device__ __forceinline__ void unpack2(ull v, float& lo, float& hi) {
    asm("mov.b64 {%0, %1}, %2;" : "=f"(lo), "=f"(hi) : "l"(v));
}
#define FMA2(acc, a, b) asm("fma.rn.f32x2 %0, %1, %2, %0;" : "+l"(acc) : "l"(a), "l"(b))

__device__ __forceinline__ float sigf(float x) { return 1.f / (1.f + __expf(-x)); }
__device__ __forceinline__ float tanh_fast(float x) {
    return 1.f - 2.f / (__expf(2.f * x) + 1.f);
}

// P[v][j] = sum_d emb[v,d]*w_ih0[j,d] + b_ih0[j] + b_hh0[j]   (51.2 MB static)
__device__ float g_P[50000 * 256];

// ---------------------------------------------------------------------------
// Kernel 1: per-vocab input transform (unchanged).
// ---------------------------------------------------------------------------
__global__ __launch_bounds__(256)
void prep_kernel(const float* __restrict__ emb,
                 const float* __restrict__ w_ih0,
                 const float* __restrict__ b_ih0,
                 const float* __restrict__ b_hh0,
                 int V)
{
    const int E = 100;
    const int j = threadIdx.x;

    ull w[50];
    {
        const ull* wp = reinterpret_cast<const ull*>(w_ih0 + (size_t)j * E);
#pragma unroll
        for (int k = 0; k < 50; k++) w[k] = wp[k];
    }
    const float bias = b_ih0[j] + b_hh0[j];

    __shared__ __align__(16) float es[4 * 100];

    for (int v0 = blockIdx.x * 4; v0 < V; v0 += gridDim.x * 4) {
        __syncthreads();
        int nload = min(4 * E, (V - v0) * E);
        for (int idx = j; idx < nload; idx += 256) es[idx] = emb[(size_t)v0 * E + idx];
        __syncthreads();

        ull acc0 = 0, acc1 = 0, acc2 = 0, acc3 = 0;
#pragma unroll
        for (int q = 0; q < 25; q++) {
            ulonglong2 h0 = *reinterpret_cast<const ulonglong2*>(&es[0 * 100 + q * 4]);
            ulonglong2 h1 = *reinterpret_cast<const ulonglong2*>(&es[1 * 100 + q * 4]);
            ulonglong2 h2 = *reinterpret_cast<const ulonglong2*>(&es[2 * 100 + q * 4]);
            ulonglong2 h3 = *reinterpret_cast<const ulonglong2*>(&es[3 * 100 + q * 4]);
            FMA2(acc0, w[2 * q], h0.x);  FMA2(acc0, w[2 * q + 1], h0.y);
            FMA2(acc1, w[2 * q], h1.x);  FMA2(acc1, w[2 * q + 1], h1.y);
            FMA2(acc2, w[2 * q], h2.x);  FMA2(acc2, w[2 * q + 1], h2.y);
            FMA2(acc3, w[2 * q], h3.x);  FMA2(acc3, w[2 * q + 1], h3.y);
        }
        ull accs[4] = {acc0, acc1, acc2, acc3};
#pragma unroll
        for (int r = 0; r < 4; r++) {
            if (v0 + r < V) {
                float lo, hi; unpack2(accs[r], lo, hi);
                g_P[(size_t)(v0 + r) * 256 + j] = lo + hi + bias;
            }
        }
    }
}

// ---------------------------------------------------------------------------
// Dynamic-smem layout for the scan kernel.
//   wi   : w_ih1 rows, 64 floats each, 16B chunks XOR-swizzled (c ^ (j&15))
//          -> conflict-free at the 4-phase crossbar floor.
//   rest : h states + gate staging.
// ---------------------------------------------------------------------------
struct ScanSmem {
    float wi[256 * 64];     // 64 KB
    float h0s[2][64];
    float h1s[2][64];
    float sg0[2][256];
    float sg1[2][256];
};

// ---------------------------------------------------------------------------
// Kernel 2: fused 2-layer LSTM scan, split-K x2, 512 threads, CTA = 2 rows.
// Thread t: gate row j = t>>1, half h = t&1. Registers hold 32-float halves
// of w_hh0[j] and w_hh1[j] (64 regs total). w_ih1 comes from swizzled smem.
// Pair (even,odd lane) reduces dot halves via shfl_xor(1).
// ---------------------------------------------------------------------------
__global__ __launch_bounds__(512, 1)
void scan_kernel(const int*   __restrict__ x,
                 const float* __restrict__ w_hh0,
                 const float* __restrict__ w_ih1,
                 const float* __restrict__ w_hh1,
                 const float* __restrict__ b_ih1,
                 const float* __restrict__ b_hh1,
                 const float* __restrict__ fc_w,
                 const float* __restrict__ fc_b,
                 float* __restrict__ out,
                 int T)
{
    extern __shared__ __align__(16) char smem_raw[];
    ScanSmem* s = reinterpret_cast<ScanSmem*>(smem_raw);

    const int HH = 64, GG = 256;
    const int t_  = threadIdx.x;
    const int j   = t_ >> 1;       // gate row 0..255
    const int h   = t_ & 1;        // K-half
    const int b0  = blockIdx.x * 2;

    // ---- stage w_ih1 into swizzled smem (once) ----
    for (int idx = t_; idx < 256 * 16; idx += 512) {
        int row = idx >> 4, c = idx & 15;
        float4 v = *reinterpret_cast<const float4*>(w_ih1 + (size_t)row * HH + c * 4);
        int dst = c ^ (row & 15);
        *reinterpret_cast<float4*>(&s->wi[row * 64 + dst * 4]) = v;
    }

    // ---- register weights: 32-float halves of w_hh0[j], w_hh1[j] ----
    ull w0[16], wh[16];
    {
        const ull* p = reinterpret_cast<const ull*>(w_hh0 + (size_t)j * HH + h * 32);
#pragma unroll
        for (int k = 0; k < 16; k++) w0[k] = p[k];
        p = reinterpret_cast<const ull*>(w_hh1 + (size_t)j * HH + h * 32);
#pragma unroll
        for (int k = 0; k < 16; k++) wh[k] = p[k];
    }
    const float bias1 = b_ih1[j] + b_hh1[j];

    if (t_ < 128) {
        ((float*)s->h0s)[t_] = 0.f;
        ((float*)s->h1s)[t_] = 0.f;
    }
    float cst = 0.f;  // cell state: t_<128 -> layer0; t_ in [256,384) -> layer1

    const int* xb0 = x + (size_t)b0 * T;
    const int* xb1 = x + (size_t)(b0 + 1) * T;
    float curP0 = 0.f, curP1 = 0.f;
    if (h == 0) {
        curP0 = g_P[(size_t)xb0[0] * GG + j];
        curP1 = g_P[(size_t)xb1[0] * GG + j];
    }
    const int wi_base = j * 64;
    const int jsw = j & 15;
    __syncthreads();

    for (int t = 0; t < T; t++) {
        int tn = min(t + 1, T - 1);
        float nP0 = 0.f, nP1 = 0.f;
        if (h == 0) {
            nP0 = g_P[(size_t)xb0[tn] * GG + j];
            nP1 = g_P[(size_t)xb1[tn] * GG + j];
        }

        // ---- phase a: g0 = P + w_hh0.h0 ; g1 partial = bias1 + w_hh1.h1 ----
        // 4 independent 16-FMA2 chains.
        ull a0  = pack2(curP0, 0.f);
        ull a1  = pack2(curP1, 0.f);
        ull g1a = (h == 0) ? pack2(bias1, 0.f) : 0ull;
        ull g1b = 0ull;
#pragma unroll
        for (int q = 0; q < 8; q++) {
            ulonglong2 u0 = *reinterpret_cast<const ulonglong2*>(&s->h0s[0][h * 32 + q * 4]);
            ulonglong2 u1 = *reinterpret_cast<const ulonglong2*>(&s->h0s[1][h * 32 + q * 4]);
            ulonglong2 v0 = *reinterpret_cast<const ulonglong2*>(&s->h1s[0][h * 32 + q * 4]);
            ulonglong2 v1 = *reinterpret_cast<const ulonglong2*>(&s->h1s[1][h * 32 + q * 4]);
            FMA2(a0,  w0[2 * q],     u0.x);
            FMA2(a1,  w0[2 * q],     u1.x);
            FMA2(g1a, wh[2 * q],     v0.x);
            FMA2(g1b, wh[2 * q],     v1.x);
            FMA2(a0,  w0[2 * q + 1], u0.y);
            FMA2(a1,  w0[2 * q + 1], u1.y);
            FMA2(g1a, wh[2 * q + 1], v0.y);
            FMA2(g1b, wh[2 * q + 1], v1.y);
        }
        {
            float lo, hi;
            unpack2(a0, lo, hi);
            float s0 = lo + hi;
            s0 += __shfl_xor_sync(0xffffffffu, s0, 1);
            unpack2(a1, lo, hi);
            float s1 = lo + hi;
            s1 += __shfl_xor_sync(0xffffffffu, s1, 1);
            if (h == 0) { s->sg0[0][j] = s0; s->sg0[1][j] = s1; }
        }
        __syncthreads();

        // ---- phase b: layer0 LSTM cell on threads 0..127 ----
        if (t_ < 128) {
            int b = t_ >> 6, u = t_ & 63;
            float gi = s->sg0[b][u], gf = s->sg0[b][u + 64];
            float gz = s->sg0[b][u + 128], go = s->sg0[b][u + 192];
            float iv = sigf(gi), fv = sigf(gf), zv = tanh_fast(gz), ov = sigf(go);
            cst = fv * cst + iv * zv;
            s->h0s[b][u] = ov * tanh_fast(cst);
        }
        __syncthreads();

        // ---- phase c: g1 += w_ih1.h0_new (wi from swizzled smem) ----
#pragma unroll
        for (int q = 0; q < 8; q++) {
            int c = (h * 8 + q) ^ jsw;
            ulonglong2 wv = *reinterpret_cast<const ulonglong2*>(&s->wi[wi_base + c * 4]);
            ulonglong2 u0 = *reinterpret_cast<const ulonglong2*>(&s->h0s[0][h * 32 + q * 4]);
            ulonglong2 u1 = *reinterpret_cast<const ulonglong2*>(&s->h0s[1][h * 32 + q * 4]);
            FMA2(g1a, wv.x, u0.x);
            FMA2(g1b, wv.x, u1.x);
            FMA2(g1a, wv.y, u0.y);
            FMA2(g1b, wv.y, u1.y);
        }
        {
            float lo, hi;
            unpack2(g1a, lo, hi);
            float u0 = lo + hi;
            u0 += __shfl_xor_sync(0xffffffffu, u0, 1);
            unpack2(g1b, lo, hi);
            float u1 = lo + hi;
            u1 += __shfl_xor_sync(0xffffffffu, u1, 1);
            if (h == 0) { s->sg1[0][j] = u0; s->sg1[1][j] = u1 + bias1; }
        }
        __syncthreads();

        // ---- phase d: layer1 LSTM cell on threads 256..383 ----
        if (t_ >= 256 && t_ < 384) {
            int lt = t_ - 256;
            int b = lt >> 6, u = lt & 63;
            float gi = s->sg1[b][u], gf = s->sg1[b][u + 64];
            float gz = s->sg1[b][u + 128], go = s->sg1[b][u + 192];
            float iv = sigf(gi), fv = sigf(gf), zv = tanh_fast(gz), ov = sigf(go);
            cst = fv * cst + iv * zv;
            s->h1s[b][u] = ov * tanh_fast(cst);
        }
        curP0 = nP0; curP1 = nP1;
        __syncthreads();
    }

    // ---- final: out[b] = sigmoid(relu(h1_last) . fc_w + fc_b) ----
    if (t_ < 2) {
        float sacc = fc_b[0];
#pragma unroll
        for (int u = 0; u < HH; u++)
            sacc += fmaxf(s->h1s[t_][u], 0.f) * fc_w[u];
        out[b0 + t_] = sigf(sacc);
    }
}

// ---------------------------------------------------------------------------
// Launch
// ---------------------------------------------------------------------------
extern "C" void kernel_launch(void* const* d_in, const int* in_sizes, int n_in,
                              void* d_out, int out_size)
{
    const int*   x     = (const int*)  d_in[0];
    const float* emb   = (const float*)d_in[1];
    const float* w_ih0 = (const float*)d_in[2];
    const float* w_hh0 = (const float*)d_in[3];
    const float* b_ih0 = (const float*)d_in[4];
    const float* b_hh0 = (const float*)d_in[5];
    const float* w_ih1 = (const float*)d_in[6];
    const float* w_hh1 = (const float*)d_in[7];
    const float* b_ih1 = (const float*)d_in[8];
    const float* b_hh1 = (const float*)d_in[9];
    const float* fc_w  = (const float*)d_in[10];
    const float* fc_b  = (const float*)d_in[11];
    float* out = (float*)d_out;

    const int B = out_size;              // 256
    const int T = in_sizes[0] / B;       // 512
    const int E = in_sizes[2] / 256;     // 100
    const int V = in_sizes[1] / E;       // 50000

    (void)n_in; (void)E;

    static_assert(sizeof(ScanSmem) < 100 * 1024, "smem");
    cudaFuncSetAttribute(scan_kernel, cudaFuncAttributeMaxDynamicSharedMemorySize,
                         (int)sizeof(ScanSmem));

    prep_kernel<<<296, 256>>>(emb, w_ih0, b_ih0, b_hh0, V);
    scan_kernel<<<B / 2, 512, sizeof(ScanSmem)>>>(x, w_hh0, w_ih1, w_hh1,
                                                  b_ih1, b_hh1, fc_w, fc_b, out, T);
}

// round 5
// speedup vs baseline: 1.6159x; 1.6159x over previous
#include <cuda_runtime.h>
#include <cstdint>

typedef unsigned long long ull;

__device__ __forceinline__ ull pack2(float lo, float hi) {
    ull r; asm("mov.b64 %0, {%1, %2};" : "=l"(r) : "f"(lo), "f"(hi)); return r;
}
__device__ __forceinline__ void unpack2(ull v, float& lo, float& hi) {
    asm("mov.b64 {%0, %1}, %2;" : "=f"(lo), "=f"(hi) : "l"(v));
}
#define FMA2(acc, a, b) asm("fma.rn.f32x2 %0, %1, %2, %0;" : "+l"(acc) : "l"(a), "l"(b))

__device__ __forceinline__ float sigf(float x) { return 1.f / (1.f + __expf(-x)); }
__device__ __forceinline__ float tanh_fast(float x) {
    return 1.f - 2.f / (__expf(2.f * x) + 1.f);
}

// P[v][slot], slot-permuted: slot 4u+p holds gate row p*64+u.  (51.2 MB)
__device__ float g_P[50000 * 256];

// ---------------------------------------------------------------------------
// Kernel 1: per-vocab input transform; writes permuted slots.
// ---------------------------------------------------------------------------
__global__ __launch_bounds__(256)
void prep_kernel(const float* __restrict__ emb,
                 const float* __restrict__ w_ih0,
                 const float* __restrict__ b_ih0,
                 const float* __restrict__ b_hh0,
                 int V)
{
    const int E = 100;
    const int j = threadIdx.x;
    const int slot = 4 * (j & 63) + (j >> 6);

    ull w[50];
    {
        const ull* wp = reinterpret_cast<const ull*>(w_ih0 + (size_t)j * E);
#pragma unroll
        for (int k = 0; k < 50; k++) w[k] = wp[k];
    }
    const float bias = b_ih0[j] + b_hh0[j];

    __shared__ __align__(16) float es[4 * 100];

    for (int v0 = blockIdx.x * 4; v0 < V; v0 += gridDim.x * 4) {
        __syncthreads();
        int nload = min(4 * E, (V - v0) * E);
        for (int idx = j; idx < nload; idx += 256) es[idx] = emb[(size_t)v0 * E + idx];
        __syncthreads();

        ull acc0 = 0, acc1 = 0, acc2 = 0, acc3 = 0;
#pragma unroll
        for (int q = 0; q < 25; q++) {
            ulonglong2 h0 = *reinterpret_cast<const ulonglong2*>(&es[0 * 100 + q * 4]);
            ulonglong2 h1 = *reinterpret_cast<const ulonglong2*>(&es[1 * 100 + q * 4]);
            ulonglong2 h2 = *reinterpret_cast<const ulonglong2*>(&es[2 * 100 + q * 4]);
            ulonglong2 h3 = *reinterpret_cast<const ulonglong2*>(&es[3 * 100 + q * 4]);
            FMA2(acc0, w[2 * q], h0.x);  FMA2(acc0, w[2 * q + 1], h0.y);
            FMA2(acc1, w[2 * q], h1.x);  FMA2(acc1, w[2 * q + 1], h1.y);
            FMA2(acc2, w[2 * q], h2.x);  FMA2(acc2, w[2 * q + 1], h2.y);
            FMA2(acc3, w[2 * q], h3.x);  FMA2(acc3, w[2 * q + 1], h3.y);
        }
        ull accs[4] = {acc0, acc1, acc2, acc3};
#pragma unroll
        for (int r = 0; r < 4; r++) {
            if (v0 + r < V) {
                float lo, hi; unpack2(accs[r], lo, hi);
                g_P[(size_t)(v0 + r) * 256 + slot] = lo + hi + bias;
            }
        }
    }
}

// ---------------------------------------------------------------------------
// Kernel 2: fused 2-layer LSTM scan, quad-remapped gates.
// 256 threads, CTA = 2 batch rows. Thread t = 4u+p owns gate row p*64+u
// (p = gate i/f/g/o) for both rows; all 3 weight rows in registers.
// Cells are intra-warp (smem act staging + __syncwarp + LDS.128).
// Only 2 CTA barriers per step.
// ---------------------------------------------------------------------------
__global__ __launch_bounds__(256, 1)
void scan_kernel(const int*   __restrict__ x,
                 const float* __restrict__ w_hh0,
                 const float* __restrict__ w_ih1,
                 const float* __restrict__ w_hh1,
                 const float* __restrict__ b_ih1,
                 const float* __restrict__ b_hh1,
                 const float* __restrict__ fc_w,
                 const float* __restrict__ fc_b,
                 float* __restrict__ out,
                 int T)
{
    const int HH = 64;
    const int t_ = threadIdx.x;
    const int p  = t_ & 3;        // gate type: 0=i 1=f 2=g 3=o
    const int u  = t_ >> 2;       // unit 0..63
    const int r  = p * 64 + u;    // original gate row
    const int b0 = blockIdx.x * 2;

    __shared__ __align__(16) float h0s[2][HH];
    __shared__ __align__(16) float h1s[2][HH];
    __shared__ __align__(16) float sact[2][256];   // activated gates, slot 4u+p
    __shared__ int sx[2][512];                     // token ids

    ull w0[32], wi[32], wh[32];
    {
        const ull* q0 = reinterpret_cast<const ull*>(w_hh0 + (size_t)r * HH);
        const ull* q1 = reinterpret_cast<const ull*>(w_ih1 + (size_t)r * HH);
        const ull* q2 = reinterpret_cast<const ull*>(w_hh1 + (size_t)r * HH);
#pragma unroll
        for (int k = 0; k < 32; k++) { w0[k] = q0[k]; wi[k] = q1[k]; wh[k] = q2[k]; }
    }
    const float bias1 = b_ih1[r] + b_hh1[r];

    for (int i = t_; i < T; i += 256) {
        sx[0][i] = x[(size_t)b0 * T + i];
        sx[1][i] = x[(size_t)(b0 + 1) * T + i];
    }
    if (t_ < 2 * HH) {
        ((float*)h0s)[t_] = 0.f;
        ((float*)h1s)[t_] = 0.f;
    }
    // Lane p<2 keeps cell states for batch row p: c_l0 (layer0), c_l1 (layer1).
    float c_l0 = 0.f, c_l1 = 0.f;
    __syncthreads();

    float curP0 = g_P[(size_t)sx[0][0] * 256 + t_];
    float curP1 = g_P[(size_t)sx[1][0] * 256 + t_];

    for (int t = 0; t < T; t++) {
        int tn = min(t + 1, T - 1);
        float nP0 = g_P[(size_t)sx[0][tn] * 256 + t_];
        float nP1 = g_P[(size_t)sx[1][tn] * 256 + t_];

        // ---- phase a: g0 = P + w_hh0.h0_prev ; g1 = bias1 + w_hh1.h1_prev
        ull a0  = pack2(curP0, 0.f);
        ull a1  = pack2(curP1, 0.f);
        ull g1a = pack2(bias1, 0.f);
        ull g1b = 0ull;                 // bias1 for row 1 added in phase c sum
#pragma unroll
        for (int q = 0; q < 16; q++) {
            ulonglong2 u0 = *reinterpret_cast<const ulonglong2*>(&h0s[0][q * 4]);
            ulonglong2 u1 = *reinterpret_cast<const ulonglong2*>(&h0s[1][q * 4]);
            ulonglong2 v0 = *reinterpret_cast<const ulonglong2*>(&h1s[0][q * 4]);
            ulonglong2 v1 = *reinterpret_cast<const ulonglong2*>(&h1s[1][q * 4]);
            FMA2(a0,  w0[2 * q],     u0.x);
            FMA2(a1,  w0[2 * q],     u1.x);
            FMA2(g1a, wh[2 * q],     v0.x);
            FMA2(g1b, wh[2 * q],     v1.x);
            FMA2(a0,  w0[2 * q + 1], u0.y);
            FMA2(a1,  w0[2 * q + 1], u1.y);
            FMA2(g1a, wh[2 * q + 1], v0.y);
            FMA2(g1b, wh[2 * q + 1], v1.y);
        }
        {
            float lo, hi;
            unpack2(a0, lo, hi); float s0 = lo + hi;
            unpack2(a1, lo, hi); float s1 = lo + hi;
            sact[0][t_] = (p == 2) ? tanh_fast(s0) : sigf(s0);
            sact[1][t_] = (p == 2) ? tanh_fast(s1) : sigf(s1);
        }
        __syncwarp();

        // ---- layer0 cell (intra-warp): lane p<2 handles batch row p ----
        if (p < 2) {
            float4 g4 = *reinterpret_cast<const float4*>(&sact[p][u * 4]);
            c_l0 = g4.y * c_l0 + g4.x * g4.z;          // f*c + i*g
            h0s[p][u] = g4.w * tanh_fast(c_l0);        // o*tanh(c)
        }
        __syncthreads();   // publish h0_new CTA-wide

        // ---- phase c: g1 += w_ih1.h0_new (4 chains to clear RAW) ----
        ull g1c = 0ull, g1d = 0ull;
#pragma unroll
        for (int q = 0; q < 8; q++) {
            ulonglong2 u0a = *reinterpret_cast<const ulonglong2*>(&h0s[0][q * 8]);
            ulonglong2 u0b = *reinterpret_cast<const ulonglong2*>(&h0s[0][q * 8 + 4]);
            ulonglong2 u1a = *reinterpret_cast<const ulonglong2*>(&h0s[1][q * 8]);
            ulonglong2 u1b = *reinterpret_cast<const ulonglong2*>(&h0s[1][q * 8 + 4]);
            FMA2(g1a, wi[4 * q],     u0a.x);
            FMA2(g1b, wi[4 * q],     u1a.x);
            FMA2(g1c, wi[4 * q + 2], u0b.x);
            FMA2(g1d, wi[4 * q + 2], u1b.x);
            FMA2(g1a, wi[4 * q + 1], u0a.y);
            FMA2(g1b, wi[4 * q + 1], u1a.y);
            FMA2(g1c, wi[4 * q + 3], u0b.y);
            FMA2(g1d, wi[4 * q + 3], u1b.y);
        }
        {
            float lo, hi, lo2, hi2;
            unpack2(g1a, lo, hi); unpack2(g1c, lo2, hi2);
            float s0 = (lo + hi) + (lo2 + hi2);
            unpack2(g1b, lo, hi); unpack2(g1d, lo2, hi2);
            float s1 = (lo + hi) + (lo2 + hi2) + bias1;   // FIX: bias1 for row 1
            sact[0][t_] = (p == 2) ? tanh_fast(s0) : sigf(s0);
            sact[1][t_] = (p == 2) ? tanh_fast(s1) : sigf(s1);
        }
        __syncwarp();

        // ---- layer1 cell (intra-warp): lane p<2 handles batch row p ----
        if (p < 2) {
            float4 g4 = *reinterpret_cast<const float4*>(&sact[p][u * 4]);
            c_l1 = g4.y * c_l1 + g4.x * g4.z;
            h1s[p][u] = g4.w * tanh_fast(c_l1);
        }
        curP0 = nP0; curP1 = nP1;
        __syncthreads();   // publish h1_new + protect next step's reads
    }

    // ---- final: out[b] = sigmoid(relu(h1_last) . fc_w + fc_b) ----
    if (t_ < 2) {
        float sacc = fc_b[0];
#pragma unroll
        for (int uu = 0; uu < HH; uu++)
            sacc += fmaxf(h1s[t_][uu], 0.f) * fc_w[uu];
        out[b0 + t_] = sigf(sacc);
    }
}

// ---------------------------------------------------------------------------
// Launch
// ---------------------------------------------------------------------------
extern "C" void kernel_launch(void* const* d_in, const int* in_sizes, int n_in,
                              void* d_out, int out_size)
{
    const int*   x     = (const int*)  d_in[0];
    const float* emb   = (const float*)d_in[1];
    const float* w_ih0 = (const float*)d_in[2];
    const float* w_hh0 = (const float*)d_in[3];
    const float* b_ih0 = (const float*)d_in[4];
    const float* b_hh0 = (const float*)d_in[5];
    const float* w_ih1 = (const float*)d_in[6];
    const float* w_hh1 = (const float*)d_in[7];
    const float* b_ih1 = (const float*)d_in[8];
    const float* b_hh1 = (const float*)d_in[9];
    const float* fc_w  = (const float*)d_in[10];
    const float* fc_b  = (const float*)d_in[11];
    float* out = (float*)d_out;

    const int B = out_size;              // 256
    const int T = in_sizes[0] / B;       // 512
    const int E = in_sizes[2] / 256;     // 100
    const int V = in_sizes[1] / E;       // 50000

    (void)n_in; (void)E;

    prep_kernel<<<296, 256>>>(emb, w_ih0, b_ih0, b_hh0, V);
    scan_kernel<<<B / 2, 256>>>(x, w_hh0, w_ih1, w_hh1, b_ih1, b_hh1,
                                fc_w, fc_b, out, T);
}

// round 6
// speedup vs baseline: 2.4636x; 1.5246x over previous
#include <cuda_runtime.h>
#include <cstdint>

typedef unsigned long long ull;

__device__ __forceinline__ ull pack2(float lo, float hi) {
    ull r; asm("mov.b64 %0, {%1, %2};" : "=l"(r) : "f"(lo), "f"(hi)); return r;
}
__device__ __forceinline__ void unpack2(ull v, float& lo, float& hi) {
    asm("mov.b64 {%0, %1}, %2;" : "=f"(lo), "=f"(hi) : "l"(v));
}
#define FMA2(acc, a, b) asm("fma.rn.f32x2 %0, %1, %2, %0;" : "+l"(acc) : "l"(a), "l"(b))

// Fast activations: MUFU-based exp and reciprocal (~1e-7 abs err, fine at 1e-3 tol).
__device__ __forceinline__ float sigf(float x) {
    return __fdividef(1.f, 1.f + __expf(-x));
}
__device__ __forceinline__ float tanh_fast(float x) {
    return 1.f - __fdividef(2.f, __expf(2.f * x) + 1.f);
}

// P[v][slot], slot-permuted: slot 4u+p holds gate row p*64+u.  (51.2 MB)
__device__ float g_P[50000 * 256];

// ---------------------------------------------------------------------------
// Kernel 1: per-vocab input transform; writes permuted slots.
// ---------------------------------------------------------------------------
__global__ __launch_bounds__(256)
void prep_kernel(const float* __restrict__ emb,
                 const float* __restrict__ w_ih0,
                 const float* __restrict__ b_ih0,
                 const float* __restrict__ b_hh0,
                 int V)
{
    const int E = 100;
    const int j = threadIdx.x;
    const int slot = 4 * (j & 63) + (j >> 6);

    ull w[50];
    {
        const ull* wp = reinterpret_cast<const ull*>(w_ih0 + (size_t)j * E);
#pragma unroll
        for (int k = 0; k < 50; k++) w[k] = wp[k];
    }
    const float bias = b_ih0[j] + b_hh0[j];

    __shared__ __align__(16) float es[4 * 100];

    for (int v0 = blockIdx.x * 4; v0 < V; v0 += gridDim.x * 4) {
        __syncthreads();
        int nload = min(4 * E, (V - v0) * E);
        for (int idx = j; idx < nload; idx += 256) es[idx] = emb[(size_t)v0 * E + idx];
        __syncthreads();

        ull acc0 = 0, acc1 = 0, acc2 = 0, acc3 = 0;
#pragma unroll
        for (int q = 0; q < 25; q++) {
            ulonglong2 h0 = *reinterpret_cast<const ulonglong2*>(&es[0 * 100 + q * 4]);
            ulonglong2 h1 = *reinterpret_cast<const ulonglong2*>(&es[1 * 100 + q * 4]);
            ulonglong2 h2 = *reinterpret_cast<const ulonglong2*>(&es[2 * 100 + q * 4]);
            ulonglong2 h3 = *reinterpret_cast<const ulonglong2*>(&es[3 * 100 + q * 4]);
            FMA2(acc0, w[2 * q], h0.x);  FMA2(acc0, w[2 * q + 1], h0.y);
            FMA2(acc1, w[2 * q], h1.x);  FMA2(acc1, w[2 * q + 1], h1.y);
            FMA2(acc2, w[2 * q], h2.x);  FMA2(acc2, w[2 * q + 1], h2.y);
            FMA2(acc3, w[2 * q], h3.x);  FMA2(acc3, w[2 * q + 1], h3.y);
        }
        ull accs[4] = {acc0, acc1, acc2, acc3};
#pragma unroll
        for (int r = 0; r < 4; r++) {
            if (v0 + r < V) {
                float lo, hi; unpack2(accs[r], lo, hi);
                g_P[(size_t)(v0 + r) * 256 + slot] = lo + hi + bias;
            }
        }
    }
}

// ---------------------------------------------------------------------------
// Kernel 2: fused 2-layer LSTM scan, layer-1 pipelined one step behind.
// Iteration t computes h0(t) and h1(t-1); all three matvecs read only
// iteration-start state -> one fused FMA2 block, one CTA barrier per step.
// Thread t_ = 4u+p owns gate row p*64+u of all 3 matrices (registers).
// Cells: lanes p<2 -> layer0 row p; lanes p>=2 -> layer1 row p-2.
// h state double-buffered (read t&1, write (t+1)&1).
// ---------------------------------------------------------------------------
__global__ __launch_bounds__(256, 1)
void scan_kernel(const int*   __restrict__ x,
                 const float* __restrict__ w_hh0,
                 const float* __restrict__ w_ih1,
                 const float* __restrict__ w_hh1,
                 const float* __restrict__ b_ih1,
                 const float* __restrict__ b_hh1,
                 const float* __restrict__ fc_w,
                 const float* __restrict__ fc_b,
                 float* __restrict__ out,
                 int T)
{
    const int HH = 64;
    const int t_ = threadIdx.x;
    const int p  = t_ & 3;        // gate type: 0=i 1=f 2=g 3=o
    const int u  = t_ >> 2;       // unit 0..63
    const int r  = p * 64 + u;    // original gate row
    const int b0 = blockIdx.x * 2;

    __shared__ __align__(16) float h0s[2][2][HH];   // [buf][row][unit]
    __shared__ __align__(16) float h1s[2][2][HH];
    __shared__ __align__(16) float sact0[2][256];   // layer0 acts, slot 4u+p
    __shared__ __align__(16) float sact1[2][256];   // layer1 acts
    __shared__ int sx[2][512];

    ull w0[32], wi[32], wh[32];
    {
        const ull* q0 = reinterpret_cast<const ull*>(w_hh0 + (size_t)r * HH);
        const ull* q1 = reinterpret_cast<const ull*>(w_ih1 + (size_t)r * HH);
        const ull* q2 = reinterpret_cast<const ull*>(w_hh1 + (size_t)r * HH);
#pragma unroll
        for (int k = 0; k < 32; k++) { w0[k] = q0[k]; wi[k] = q1[k]; wh[k] = q2[k]; }
    }
    const float bias1 = b_ih1[r] + b_hh1[r];

    for (int i = t_; i < T; i += 256) {
        sx[0][i] = x[(size_t)b0 * T + i];
        sx[1][i] = x[(size_t)(b0 + 1) * T + i];
    }
    if (t_ < 2 * 2 * HH) {            // zero both buffers of both layers
        ((float*)h0s)[t_] = 0.f;
        ((float*)h1s)[t_] = 0.f;
    }
    // Lane roles: p<2 hold c_l0 for batch row p; p>=2 hold c_l1 for row p-2.
    float cstate = 0.f;
    __syncthreads();

    float curP0 = g_P[(size_t)sx[0][0] * 256 + t_];
    float curP1 = g_P[(size_t)sx[1][0] * 256 + t_];

    for (int t = 0; t <= T; t++) {
        int cur = t & 1, nxt = cur ^ 1;
        int tn = min(t + 1, T - 1);
        float nP0 = g_P[(size_t)sx[0][tn] * 256 + t_];
        float nP1 = g_P[(size_t)sx[1][tn] * 256 + t_];

        const float* H0 = &h0s[cur][0][0];   // h0(t-1), rows 0/1 at +0/+64
        const float* H1 = &h1s[cur][0][0];   // h1(t-2)

        // ---- fused matvecs: g0 = P + w_hh0.h0 ; g1 = bias1 + w_ih1.h0 + w_hh1.h1
        ull a0  = pack2(curP0, 0.f);
        ull a1  = pack2(curP1, 0.f);
        ull g1a = pack2(bias1, 0.f);     // row0: w_ih1 part
        ull g1b = pack2(bias1, 0.f);     // row1: w_ih1 part  (bias only once per row)
        ull g1c = 0ull;                  // row0: w_hh1 part
        ull g1d = 0ull;                  // row1: w_hh1 part
        // note: bias1 added twice? NO - g1a and g1b are different rows. OK.
#pragma unroll
        for (int q = 0; q < 16; q++) {
            ulonglong2 u0 = *reinterpret_cast<const ulonglong2*>(H0 + q * 4);
            ulonglong2 u1 = *reinterpret_cast<const ulonglong2*>(H0 + 64 + q * 4);
            ulonglong2 v0 = *reinterpret_cast<const ulonglong2*>(H1 + q * 4);
            ulonglong2 v1 = *reinterpret_cast<const ulonglong2*>(H1 + 64 + q * 4);
            FMA2(a0,  w0[2 * q],     u0.x);
            FMA2(a1,  w0[2 * q],     u1.x);
            FMA2(g1a, wi[2 * q],     u0.x);
            FMA2(g1b, wi[2 * q],     u1.x);
            FMA2(g1c, wh[2 * q],     v0.x);
            FMA2(g1d, wh[2 * q],     v1.x);
            FMA2(a0,  w0[2 * q + 1], u0.y);
            FMA2(a1,  w0[2 * q + 1], u1.y);
            FMA2(g1a, wi[2 * q + 1], u0.y);
            FMA2(g1b, wi[2 * q + 1], u1.y);
            FMA2(g1c, wh[2 * q + 1], v0.y);
            FMA2(g1d, wh[2 * q + 1], v1.y);
        }
        {
            float lo, hi, lo2, hi2;
            unpack2(a0, lo, hi);  float s0 = lo + hi;
            unpack2(a1, lo, hi);  float s1 = lo + hi;
            unpack2(g1a, lo, hi); unpack2(g1c, lo2, hi2);
            float v0 = (lo + hi) + (lo2 + hi2);
            unpack2(g1b, lo, hi); unpack2(g1d, lo2, hi2);
            float v1 = (lo + hi) + (lo2 + hi2);
            if (p == 2) {
                sact0[0][t_] = tanh_fast(s0);  sact0[1][t_] = tanh_fast(s1);
                sact1[0][t_] = tanh_fast(v0);  sact1[1][t_] = tanh_fast(v1);
            } else {
                sact0[0][t_] = sigf(s0);  sact0[1][t_] = sigf(s1);
                sact1[0][t_] = sigf(v0);  sact1[1][t_] = sigf(v1);
            }
        }
        __syncwarp();   // sact quads are intra-warp

        // ---- cells: p<2 -> layer0 (valid t<T); p>=2 -> layer1 (valid t>=1)
        if (p < 2) {
            if (t < T) {
                float4 g4 = *reinterpret_cast<const float4*>(&sact0[p][u * 4]);
                cstate = g4.y * cstate + g4.x * g4.z;
                h0s[nxt][p][u] = g4.w * tanh_fast(cstate);
            }
        } else {
            if (t >= 1) {
                float4 g4 = *reinterpret_cast<const float4*>(&sact1[p - 2][u * 4]);
                cstate = g4.y * cstate + g4.x * g4.z;
                h1s[nxt][p - 2][u] = g4.w * tanh_fast(cstate);
            }
        }
        curP0 = nP0; curP1 = nP1;
        __syncthreads();   // publish h(nxt); also fences sact WAR for next iter
    }

    // ---- final: out[b] = sigmoid(relu(h1(T-1)) . fc_w + fc_b) ----
    // Last write was at iteration t=T into buffer (T+1)&1.
    if (t_ < 2) {
        const float* hf = &h1s[(T + 1) & 1][t_][0];
        float sacc = fc_b[0];
#pragma unroll
        for (int uu = 0; uu < HH; uu++)
            sacc += fmaxf(hf[uu], 0.f) * fc_w[uu];
        out[b0 + t_] = sigf(sacc);
    }
}

// ---------------------------------------------------------------------------
// Launch
// ---------------------------------------------------------------------------
extern "C" void kernel_launch(void* const* d_in, const int* in_sizes, int n_in,
                              void* d_out, int out_size)
{
    const int*   x     = (const int*)  d_in[0];
    const float* emb   = (const float*)d_in[1];
    const float* w_ih0 = (const float*)d_in[2];
    const float* w_hh0 = (const float*)d_in[3];
    const float* b_ih0 = (const float*)d_in[4];
    const float* b_hh0 = (const float*)d_in[5];
    const float* w_ih1 = (const float*)d_in[6];
    const float* w_hh1 = (const float*)d_in[7];
    const float* b_ih1 = (const float*)d_in[8];
    const float* b_hh1 = (const float*)d_in[9];
    const float* fc_w  = (const float*)d_in[10];
    const float* fc_b  = (const float*)d_in[11];
    float* out = (float*)d_out;

    const int B = out_size;              // 256
    const int T = in_sizes[0] / B;       // 512
    const int E = in_sizes[2] / 256;     // 100
    const int V = in_sizes[1] / E;       // 50000

    (void)n_in; (void)E;

    prep_kernel<<<296, 256>>>(emb, w_ih0, b_ih0, b_hh0, V);
    scan_kernel<<<B / 2, 256>>>(x, w_hh0, w_ih1, w_hh1, b_ih1, b_hh1,
                                fc_w, fc_b, out, T);
}

// round 7
// speedup vs baseline: 2.5919x; 1.0521x over previous
#include <cuda_runtime.h>
#include <cstdint>

typedef unsigned long long ull;

__device__ __forceinline__ ull pack2(float lo, float hi) {
    ull r; asm("mov.b64 %0, {%1, %2};" : "=l"(r) : "f"(lo), "f"(hi)); return r;
}
__device__ __forceinline__ void unpack2(ull v, float& lo, float& hi) {
    asm("mov.b64 {%0, %1}, %2;" : "=f"(lo), "=f"(hi) : "l"(v));
}
#define FMA2(acc, a, b) asm("fma.rn.f32x2 %0, %1, %2, %0;" : "+l"(acc) : "l"(a), "l"(b))
#define ADD2(out, a, b) asm("add.rn.f32x2 %0, %1, %2;" : "=l"(out) : "l"(a), "l"(b))

// Single-MUFU tanh (sm_75+). Internal use only.
__device__ __forceinline__ float tanh_approx(float x) {
    float y; asm("tanh.approx.f32 %0, %1;" : "=f"(y) : "f"(x)); return y;
}
// Exact-ish sigmoid for the final output only.
__device__ __forceinline__ float sigf(float x) {
    return __fdividef(1.f, 1.f + __expf(-x));
}

// P[v][slot], slot-permuted: slot 4u+p holds gate row p*64+u.  (51.2 MB)
__device__ float g_P[50000 * 256];

// ---------------------------------------------------------------------------
// Kernel 1: per-vocab input transform; writes permuted slots.
// ---------------------------------------------------------------------------
__global__ __launch_bounds__(256)
void prep_kernel(const float* __restrict__ emb,
                 const float* __restrict__ w_ih0,
                 const float* __restrict__ b_ih0,
                 const float* __restrict__ b_hh0,
                 int V)
{
    const int E = 100;
    const int j = threadIdx.x;
    const int slot = 4 * (j & 63) + (j >> 6);

    ull w[50];
    {
        const ull* wp = reinterpret_cast<const ull*>(w_ih0 + (size_t)j * E);
#pragma unroll
        for (int k = 0; k < 50; k++) w[k] = wp[k];
    }
    const float bias = b_ih0[j] + b_hh0[j];

    __shared__ __align__(16) float es[4 * 100];

    for (int v0 = blockIdx.x * 4; v0 < V; v0 += gridDim.x * 4) {
        __syncthreads();
        int nload = min(4 * E, (V - v0) * E);
        for (int idx = j; idx < nload; idx += 256) es[idx] = emb[(size_t)v0 * E + idx];
        __syncthreads();

        ull acc0 = 0, acc1 = 0, acc2 = 0, acc3 = 0;
#pragma unroll
        for (int q = 0; q < 25; q++) {
            ulonglong2 h0 = *reinterpret_cast<const ulonglong2*>(&es[0 * 100 + q * 4]);
            ulonglong2 h1 = *reinterpret_cast<const ulonglong2*>(&es[1 * 100 + q * 4]);
            ulonglong2 h2 = *reinterpret_cast<const ulonglong2*>(&es[2 * 100 + q * 4]);
            ulonglong2 h3 = *reinterpret_cast<const ulonglong2*>(&es[3 * 100 + q * 4]);
            FMA2(acc0, w[2 * q], h0.x);  FMA2(acc0, w[2 * q + 1], h0.y);
            FMA2(acc1, w[2 * q], h1.x);  FMA2(acc1, w[2 * q + 1], h1.y);
            FMA2(acc2, w[2 * q], h2.x);  FMA2(acc2, w[2 * q + 1], h2.y);
            FMA2(acc3, w[2 * q], h3.x);  FMA2(acc3, w[2 * q + 1], h3.y);
        }
        ull accs[4] = {acc0, acc1, acc2, acc3};
#pragma unroll
        for (int r = 0; r < 4; r++) {
            if (v0 + r < V) {
                float lo, hi; unpack2(accs[r], lo, hi);
                g_P[(size_t)(v0 + r) * 256 + slot] = lo + hi + bias;
            }
        }
    }
}

// ---------------------------------------------------------------------------
// Kernel 2: fused 2-layer LSTM scan, layer-1 pipelined one step behind.
// Iteration t computes h0(t) and h1(t-1); one fused FMA2 block, one CTA
// barrier per step. Thread t_ = 4u+p owns gate row p*64+u of all 3 matrices
// (registers). Activations via single-MUFU tanh.approx (sigmoid by identity).
// ---------------------------------------------------------------------------
__global__ __launch_bounds__(256, 1)
void scan_kernel(const int*   __restrict__ x,
                 const float* __restrict__ w_hh0,
                 const float* __restrict__ w_ih1,
                 const float* __restrict__ w_hh1,
                 const float* __restrict__ b_ih1,
                 const float* __restrict__ b_hh1,
                 const float* __restrict__ fc_w,
                 const float* __restrict__ fc_b,
                 float* __restrict__ out,
                 int T)
{
    const int HH = 64;
    const int t_ = threadIdx.x;
    const int p  = t_ & 3;        // gate type: 0=i 1=f 2=g 3=o
    const int u  = t_ >> 2;       // unit 0..63
    const int r  = p * 64 + u;    // original gate row
    const int b0 = blockIdx.x * 2;
    const bool is_g = (p == 2);

    __shared__ __align__(16) float h0s[2][2][HH];   // [buf][row][unit]
    __shared__ __align__(16) float h1s[2][2][HH];
    __shared__ __align__(16) float sact0[2][256];   // layer0 acts, slot 4u+p
    __shared__ __align__(16) float sact1[2][256];   // layer1 acts
    __shared__ int sx[2][512];

    ull w0[32], wi[32], wh[32];
    {
        const ull* q0 = reinterpret_cast<const ull*>(w_hh0 + (size_t)r * HH);
        const ull* q1 = reinterpret_cast<const ull*>(w_ih1 + (size_t)r * HH);
        const ull* q2 = reinterpret_cast<const ull*>(w_hh1 + (size_t)r * HH);
#pragma unroll
        for (int k = 0; k < 32; k++) { w0[k] = q0[k]; wi[k] = q1[k]; wh[k] = q2[k]; }
    }
    const float bias1 = b_ih1[r] + b_hh1[r];

    for (int i = t_; i < T; i += 256) {
        sx[0][i] = x[(size_t)b0 * T + i];
        sx[1][i] = x[(size_t)(b0 + 1) * T + i];
    }
    if (t_ < 2 * 2 * HH) {            // zero both buffers of both layers
        ((float*)h0s)[t_] = 0.f;
        ((float*)h1s)[t_] = 0.f;
    }
    // Lane roles: p<2 hold c_l0 for batch row p; p>=2 hold c_l1 for row p-2.
    float cstate = 0.f;
    __syncthreads();

    float curP0 = g_P[(size_t)sx[0][0] * 256 + t_];
    float curP1 = g_P[(size_t)sx[1][0] * 256 + t_];

    // Gate-activation: pre-scale argument for sigmoid gates (0.5x), then one
    // tanh.approx, then affine for sigmoid gates. Branchless per gate type.
    const float argscale = is_g ? 1.f : 0.5f;
    const float resmul   = is_g ? 1.f : 0.5f;
    const float resadd   = is_g ? 0.f : 0.5f;

    for (int t = 0; t <= T; t++) {
        int cur = t & 1, nxt = cur ^ 1;
        int tn = min(t + 1, T - 1);
        float nP0 = g_P[(size_t)sx[0][tn] * 256 + t_];
        float nP1 = g_P[(size_t)sx[1][tn] * 256 + t_];

        const float* H0 = &h0s[cur][0][0];   // h0(t-1), rows 0/1 at +0/+64
        const float* H1 = &h1s[cur][0][0];   // h1(t-2)

        // ---- fused matvecs: g0 = P + w_hh0.h0 ; g1 = bias1 + w_ih1.h0 + w_hh1.h1
        ull a0  = pack2(curP0, 0.f);
        ull a1  = pack2(curP1, 0.f);
        ull g1a = pack2(bias1, 0.f);     // row0: w_ih1 part
        ull g1b = pack2(bias1, 0.f);     // row1: w_ih1 part
        ull g1c = 0ull;                  // row0: w_hh1 part
        ull g1d = 0ull;                  // row1: w_hh1 part
#pragma unroll
        for (int q = 0; q < 16; q++) {
            ulonglong2 u0 = *reinterpret_cast<const ulonglong2*>(H0 + q * 4);
            ulonglong2 u1 = *reinterpret_cast<const ulonglong2*>(H0 + 64 + q * 4);
            ulonglong2 v0 = *reinterpret_cast<const ulonglong2*>(H1 + q * 4);
            ulonglong2 v1 = *reinterpret_cast<const ulonglong2*>(H1 + 64 + q * 4);
            FMA2(a0,  w0[2 * q],     u0.x);
            FMA2(a1,  w0[2 * q],     u1.x);
            FMA2(g1a, wi[2 * q],     u0.x);
            FMA2(g1b, wi[2 * q],     u1.x);
            FMA2(g1c, wh[2 * q],     v0.x);
            FMA2(g1d, wh[2 * q],     v1.x);
            FMA2(a0,  w0[2 * q + 1], u0.y);
            FMA2(a1,  w0[2 * q + 1], u1.y);
            FMA2(g1a, wi[2 * q + 1], u0.y);
            FMA2(g1b, wi[2 * q + 1], u1.y);
            FMA2(g1c, wh[2 * q + 1], v0.y);
            FMA2(g1d, wh[2 * q + 1], v1.y);
        }
        {
            // packed combines, then scalar finish
            ull gr0, gr1;
            ADD2(gr0, g1a, g1c);
            ADD2(gr1, g1b, g1d);
            float lo, hi;
            unpack2(a0, lo, hi);  float s0 = lo + hi;
            unpack2(a1, lo, hi);  float s1 = lo + hi;
            unpack2(gr0, lo, hi); float v0 = lo + hi;
            unpack2(gr1, lo, hi); float v1 = lo + hi;
            sact0[0][t_] = fmaf(tanh_approx(s0 * argscale), resmul, resadd);
            sact0[1][t_] = fmaf(tanh_approx(s1 * argscale), resmul, resadd);
            sact1[0][t_] = fmaf(tanh_approx(v0 * argscale), resmul, resadd);
            sact1[1][t_] = fmaf(tanh_approx(v1 * argscale), resmul, resadd);
        }
        __syncwarp();   // sact quads are intra-warp

        // ---- cells: p<2 -> layer0 (valid t<T); p>=2 -> layer1 (valid t>=1)
        if (p < 2) {
            if (t < T) {
                float4 g4 = *reinterpret_cast<const float4*>(&sact0[p][u * 4]);
                cstate = g4.y * cstate + g4.x * g4.z;
                h0s[nxt][p][u] = g4.w * tanh_approx(cstate);
            }
        } else {
            if (t >= 1) {
                float4 g4 = *reinterpret_cast<const float4*>(&sact1[p - 2][u * 4]);
                cstate = g4.y * cstate + g4.x * g4.z;
                h1s[nxt][p - 2][u] = g4.w * tanh_approx(cstate);
            }
        }
        curP0 = nP0; curP1 = nP1;
        __syncthreads();   // publish h(nxt); also fences sact WAR for next iter
    }

    // ---- final: out[b] = sigmoid(relu(h1(T-1)) . fc_w + fc_b) ----
    if (t_ < 2) {
        const float* hf = &h1s[(T + 1) & 1][t_][0];
        float sacc = fc_b[0];
#pragma unroll
        for (int uu = 0; uu < HH; uu++)
            sacc += fmaxf(hf[uu], 0.f) * fc_w[uu];
        out[b0 + t_] = sigf(sacc);
    }
}

// ---------------------------------------------------------------------------
// Launch
// ---------------------------------------------------------------------------
extern "C" void kernel_launch(void* const* d_in, const int* in_sizes, int n_in,
                              void* d_out, int out_size)
{
    const int*   x     = (const int*)  d_in[0];
    const float* emb   = (const float*)d_in[1];
    const float* w_ih0 = (const float*)d_in[2];
    const float* w_hh0 = (const float*)d_in[3];
    const float* b_ih0 = (const float*)d_in[4];
    const float* b_hh0 = (const float*)d_in[5];
    const float* w_ih1 = (const float*)d_in[6];
    const float* w_hh1 = (const float*)d_in[7];
    const float* b_ih1 = (const float*)d_in[8];
    const float* b_hh1 = (const float*)d_in[9];
    const float* fc_w  = (const float*)d_in[10];
    const float* fc_b  = (const float*)d_in[11];
    float* out = (float*)d_out;

    const int B = out_size;              // 256
    const int T = in_sizes[0] / B;       // 512
    const int E = in_sizes[2] / 256;     // 100
    const int V = in_sizes[1] / E;       // 50000

    (void)n_in; (void)E;

    prep_kernel<<<296, 256>>>(emb, w_ih0, b_ih0, b_hh0, V);
    scan_kernel<<<B / 2, 256>>>(x, w_hh0, w_ih1, w_hh1, b_ih1, b_hh1,
                                fc_w, fc_b, out, T);
}

// round 8
// speedup vs baseline: 3.2848x; 1.2674x over previous
#include <cuda_runtime.h>
#include <cstdint>

typedef unsigned long long ull;

__device__ __forceinline__ ull pack2(float lo, float hi) {
    ull r; asm("mov.b64 %0, {%1, %2};" : "=l"(r) : "f"(lo), "f"(hi)); return r;
}
__device__ __forceinline__ void unpack2(ull v, float& lo, float& hi) {
    asm("mov.b64 {%0, %1}, %2;" : "=f"(lo), "=f"(hi) : "l"(v));
}
#define FMA2(acc, a, b) asm("fma.rn.f32x2 %0, %1, %2, %0;" : "+l"(acc) : "l"(a), "l"(b))

__device__ __forceinline__ float tanh_approx(float x) {
    float y; asm("tanh.approx.f32 %0, %1;" : "=f"(y) : "f"(x)); return y;
}
__device__ __forceinline__ float sigf(float x) {           // final output only
    return __fdividef(1.f, 1.f + __expf(-x));
}

// P[v][slot], slot-permuted: slot 4u+p holds gate row p*64+u.  (51.2 MB)
__device__ float g_P[50000 * 256];

// ---------------------------------------------------------------------------
// Kernel 1: per-vocab input transform; writes permuted slots.
// ---------------------------------------------------------------------------
__global__ __launch_bounds__(256)
void prep_kernel(const float* __restrict__ emb,
                 const float* __restrict__ w_ih0,
                 const float* __restrict__ b_ih0,
                 const float* __restrict__ b_hh0,
                 int V)
{
    const int E = 100;
    const int j = threadIdx.x;
    const int slot = 4 * (j & 63) + (j >> 6);

    ull w[50];
    {
        const ull* wp = reinterpret_cast<const ull*>(w_ih0 + (size_t)j * E);
#pragma unroll
        for (int k = 0; k < 50; k++) w[k] = wp[k];
    }
    const float bias = b_ih0[j] + b_hh0[j];

    __shared__ __align__(16) float es[4 * 100];

    for (int v0 = blockIdx.x * 4; v0 < V; v0 += gridDim.x * 4) {
        __syncthreads();
        int nload = min(4 * E, (V - v0) * E);
        for (int idx = j; idx < nload; idx += 256) es[idx] = emb[(size_t)v0 * E + idx];
        __syncthreads();

        ull acc0 = 0, acc1 = 0, acc2 = 0, acc3 = 0;
#pragma unroll
        for (int q = 0; q < 25; q++) {
            ulonglong2 h0 = *reinterpret_cast<const ulonglong2*>(&es[0 * 100 + q * 4]);
            ulonglong2 h1 = *reinterpret_cast<const ulonglong2*>(&es[1 * 100 + q * 4]);
            ulonglong2 h2 = *reinterpret_cast<const ulonglong2*>(&es[2 * 100 + q * 4]);
            ulonglong2 h3 = *reinterpret_cast<const ulonglong2*>(&es[3 * 100 + q * 4]);
            FMA2(acc0, w[2 * q], h0.x);  FMA2(acc0, w[2 * q + 1], h0.y);
            FMA2(acc1, w[2 * q], h1.x);  FMA2(acc1, w[2 * q + 1], h1.y);
            FMA2(acc2, w[2 * q], h2.x);  FMA2(acc2, w[2 * q + 1], h2.y);
            FMA2(acc3, w[2 * q], h3.x);  FMA2(acc3, w[2 * q + 1], h3.y);
        }
        ull accs[4] = {acc0, acc1, acc2, acc3};
#pragma unroll
        for (int r = 0; r < 4; r++) {
            if (v0 + r < V) {
                float lo, hi; unpack2(accs[r], lo, hi);
                g_P[(size_t)(v0 + r) * 256 + slot] = lo + hi + bias;
            }
        }
    }
}

// ---------------------------------------------------------------------------
// Kernel 2: fused 2-layer LSTM scan, layer-1 pipelined one step behind,
// peeled prologue/epilogue, branchless interior cells.
//
// State vectors (vec index): 0 = layer0 row0, 1 = layer0 row1,
//                            2 = layer1 row0, 3 = layer1 row1.
// Thread t_ = 4u+p owns gate row p*64+u of w_hh0, w_ih1, w_hh1 (registers).
// Lane role p maps DIRECTLY to vec p for its cell: src &sact[p][4u],
// dst &hs[nxt][p][u] -> identical straight-line cell code on every lane.
// ---------------------------------------------------------------------------
__global__ __launch_bounds__(256, 1)
void scan_kernel(const int*   __restrict__ x,
                 const float* __restrict__ w_hh0,
                 const float* __restrict__ w_ih1,
                 const float* __restrict__ w_hh1,
                 const float* __restrict__ b_ih1,
                 const float* __restrict__ b_hh1,
                 const float* __restrict__ fc_w,
                 const float* __restrict__ fc_b,
                 float* __restrict__ out,
                 int T)
{
    const int HH = 64;
    const int t_ = threadIdx.x;
    const int p  = t_ & 3;        // gate type 0=i 1=f 2=g 3=o
    const int u  = t_ >> 2;       // unit 0..63
    const int r  = p * 64 + u;    // original gate row
    const int b0 = blockIdx.x * 2;
    const bool is_g = (p == 2);

    // Padded rows: 68 (hs) / 260 (sact) de-conflict banks; both 16B-aligned.
    __shared__ __align__(16) float hs[2][4][68];     // [buf][vec][unit]
    __shared__ __align__(16) float sact[4][260];     // [vec][slot 4u+p]
    __shared__ int sx[2][512];

    ull w0[32], wi[32], wh[32];
    {
        const ull* q0 = reinterpret_cast<const ull*>(w_hh0 + (size_t)r * HH);
        const ull* q1 = reinterpret_cast<const ull*>(w_ih1 + (size_t)r * HH);
        const ull* q2 = reinterpret_cast<const ull*>(w_hh1 + (size_t)r * HH);
#pragma unroll
        for (int k = 0; k < 32; k++) { w0[k] = q0[k]; wi[k] = q1[k]; wh[k] = q2[k]; }
    }
    const float bias1 = b_ih1[r] + b_hh1[r];

    for (int i = t_; i < T; i += 256) {
        sx[0][i] = x[(size_t)b0 * T + i];
        sx[1][i] = x[(size_t)(b0 + 1) * T + i];
    }
    for (int i = t_; i < 2 * 4 * 68; i += 256) ((float*)hs)[i] = 0.f;

    float cstate = 0.f;     // lane's cell state for its (layer,row) = vec p

    // Gate activation: sigmoid via 0.5*tanh(x/2)+0.5, tanh gate direct.
    const float argscale = is_g ? 1.f : 0.5f;
    const float resmul   = is_g ? 1.f : 0.5f;
    const float resadd   = is_g ? 0.f : 0.5f;

    const float* csrc = &sact[p][4 * (unsigned)u];   // this lane's cell gates

    __syncthreads();

    float curP0 = g_P[(size_t)sx[0][0] * 256 + t_];
    float curP1 = g_P[(size_t)sx[1][0] * 256 + t_];

    // ================= prologue t = 0: layer0 only =================
    {
        float nP0 = g_P[(size_t)sx[0][1] * 256 + t_];
        float nP1 = g_P[(size_t)sx[1][1] * 256 + t_];
        // a = P + w_hh0.0 = P
        sact[0][t_] = fmaf(tanh_approx(curP0 * argscale), resmul, resadd);
        sact[1][t_] = fmaf(tanh_approx(curP1 * argscale), resmul, resadd);
        __syncwarp();
        if (p < 2) {
            float4 g4 = *reinterpret_cast<const float4*>(csrc);
            cstate = g4.y * cstate + g4.x * g4.z;
            hs[1][p][u] = g4.w * tanh_approx(cstate);
        }
        curP0 = nP0; curP1 = nP1;
        __syncthreads();
    }

    // ================= interior t = 1 .. T-1: branchless =================
    for (int t = 1; t < T; t++) {
        int cur = t & 1, nxt = cur ^ 1;
        int tn = (t + 1 == T) ? 0 : (t + 1);          // uniform select
        float nP0 = g_P[(size_t)sx[0][tn] * 256 + t_];
        float nP1 = g_P[(size_t)sx[1][tn] * 256 + t_];

        const float* H = &hs[cur][0][0];              // vec rows at stride 68

        ull a0  = pack2(curP0, 0.f);
        ull a1  = pack2(curP1, 0.f);
        ull g1a = pack2(bias1, 0.f);
        ull g1b = pack2(bias1, 0.f);
        ull g1c = 0ull;
        ull g1d = 0ull;
#pragma unroll
        for (int q = 0; q < 16; q++) {
            ulonglong2 u0 = *reinterpret_cast<const ulonglong2*>(H + 0 * 68 + q * 4);
            ulonglong2 u1 = *reinterpret_cast<const ulonglong2*>(H + 1 * 68 + q * 4);
            ulonglong2 v0 = *reinterpret_cast<const ulonglong2*>(H + 2 * 68 + q * 4);
            ulonglong2 v1 = *reinterpret_cast<const ulonglong2*>(H + 3 * 68 + q * 4);
            FMA2(a0,  w0[2 * q],     u0.x);
            FMA2(a1,  w0[2 * q],     u1.x);
            FMA2(g1a, wi[2 * q],     u0.x);
            FMA2(g1b, wi[2 * q],     u1.x);
            FMA2(g1c, wh[2 * q],     v0.x);
            FMA2(g1d, wh[2 * q],     v1.x);
            FMA2(a0,  w0[2 * q + 1], u0.y);
            FMA2(a1,  w0[2 * q + 1], u1.y);
            FMA2(g1a, wi[2 * q + 1], u0.y);
            FMA2(g1b, wi[2 * q + 1], u1.y);
            FMA2(g1c, wh[2 * q + 1], v0.y);
            FMA2(g1d, wh[2 * q + 1], v1.y);
        }
        {
            float lo, hi, lo2, hi2;
            unpack2(a0, lo, hi);  float s0 = lo + hi;
            unpack2(a1, lo, hi);  float s1 = lo + hi;
            unpack2(g1a, lo, hi); unpack2(g1c, lo2, hi2);
            float v0 = (lo + hi) + (lo2 + hi2);
            unpack2(g1b, lo, hi); unpack2(g1d, lo2, hi2);
            float v1 = (lo + hi) + (lo2 + hi2);
            sact[0][t_] = fmaf(tanh_approx(s0 * argscale), resmul, resadd);
            sact[1][t_] = fmaf(tanh_approx(s1 * argscale), resmul, resadd);
            sact[2][t_] = fmaf(tanh_approx(v0 * argscale), resmul, resadd);
            sact[3][t_] = fmaf(tanh_approx(v1 * argscale), resmul, resadd);
        }
        __syncwarp();

        // branchless cell: every lane updates its vec p
        {
            float4 g4 = *reinterpret_cast<const float4*>(csrc);
            cstate = g4.y * cstate + g4.x * g4.z;
            hs[nxt][p][u] = g4.w * tanh_approx(cstate);
        }
        curP0 = nP0; curP1 = nP1;
        __syncthreads();
    }

    // ================= epilogue t = T: layer1 only =================
    {
        const float* H = &hs[T & 1][0][0];
        ull g1a = pack2(bias1, 0.f);
        ull g1b = pack2(bias1, 0.f);
        ull g1c = 0ull;
        ull g1d = 0ull;
#pragma unroll
        for (int q = 0; q < 16; q++) {
            ulonglong2 u0 = *reinterpret_cast<const ulonglong2*>(H + 0 * 68 + q * 4);
            ulonglong2 u1 = *reinterpret_cast<const ulonglong2*>(H + 1 * 68 + q * 4);
            ulonglong2 v0 = *reinterpret_cast<const ulonglong2*>(H + 2 * 68 + q * 4);
            ulonglong2 v1 = *reinterpret_cast<const ulonglong2*>(H + 3 * 68 + q * 4);
            FMA2(g1a, wi[2 * q],     u0.x);
            FMA2(g1b, wi[2 * q],     u1.x);
            FMA2(g1c, wh[2 * q],     v0.x);
            FMA2(g1d, wh[2 * q],     v1.x);
            FMA2(g1a, wi[2 * q + 1], u0.y);
            FMA2(g1b, wi[2 * q + 1], u1.y);
            FMA2(g1c, wh[2 * q + 1], v0.y);
            FMA2(g1d, wh[2 * q + 1], v1.y);
        }
        {
            float lo, hi, lo2, hi2;
            unpack2(g1a, lo, hi); unpack2(g1c, lo2, hi2);
            float v0 = (lo + hi) + (lo2 + hi2);
            unpack2(g1b, lo, hi); unpack2(g1d, lo2, hi2);
            float v1 = (lo + hi) + (lo2 + hi2);
            sact[2][t_] = fmaf(tanh_approx(v0 * argscale), resmul, resadd);
            sact[3][t_] = fmaf(tanh_approx(v1 * argscale), resmul, resadd);
        }
        __syncwarp();
        if (p >= 2) {
            float4 g4 = *reinterpret_cast<const float4*>(csrc);
            cstate = g4.y * cstate + g4.x * g4.z;
            hs[1][p][u] = g4.w * tanh_approx(cstate);   // h1(T-1), buf 1 (T even)
        }
        __syncthreads();
    }

    // ---- final: out[b] = sigmoid(relu(h1(T-1)) . fc_w + fc_b) ----
    if (t_ < 2) {
        const float* hf = &hs[1][2 + t_][0];
        float sacc = fc_b[0];
#pragma unroll
        for (int uu = 0; uu < HH; uu++)
            sacc += fmaxf(hf[uu], 0.f) * fc_w[uu];
        out[b0 + t_] = sigf(sacc);
    }
}

// ---------------------------------------------------------------------------
// Launch
// ---------------------------------------------------------------------------
extern "C" void kernel_launch(void* const* d_in, const int* in_sizes, int n_in,
                              void* d_out, int out_size)
{
    const int*   x     = (const int*)  d_in[0];
    const float* emb   = (const float*)d_in[1];
    const float* w_ih0 = (const float*)d_in[2];
    const float* w_hh0 = (const float*)d_in[3];
    const float* b_ih0 = (const float*)d_in[4];
    const float* b_hh0 = (const float*)d_in[5];
    const float* w_ih1 = (const float*)d_in[6];
    const float* w_hh1 = (const float*)d_in[7];
    const float* b_ih1 = (const float*)d_in[8];
    const float* b_hh1 = (const float*)d_in[9];
    const float* fc_w  = (const float*)d_in[10];
    const float* fc_b  = (const float*)d_in[11];
    float* out = (float*)d_out;

    const int B = out_size;              // 256
    const int T = in_sizes[0] / B;       // 512
    const int E = in_sizes[2] / 256;     // 100
    const int V = in_sizes[1] / E;       // 50000

    (void)n_in; (void)E;

    prep_kernel<<<296, 256>>>(emb, w_ih0, b_ih0, b_hh0, V);
    scan_kernel<<<B / 2, 256>>>(x, w_hh0, w_ih1, w_hh1, b_ih1, b_hh1,
                                fc_w, fc_b, out, T);
}